// round 11
// baseline (speedup 1.0000x reference)
#include <cuda_runtime.h>
#include <math.h>
#include <stdint.h>

#define BB 128
#define NN 512
#define KNN 16
#define E_TOT (BB*NN*KNN)      /* 1048576 edges */
#define NTILES (E_TOT/64)      /* 16384 tiles of 64 edges */
#define L1GRID 296
#define L2GRID 148
#define SGRID 512

typedef unsigned long long u64;

// ---------------- packed f32x2 helpers (sm_103a FFMA2 path) ----------------
__device__ __forceinline__ u64 pack2(float lo, float hi) {
    u64 r; asm("mov.b64 %0, {%1,%2};" : "=l"(r) : "f"(lo), "f"(hi)); return r;
}
__device__ __forceinline__ float2 unpack2(u64 v) {
    float2 r; asm("mov.b64 {%0,%1}, %2;" : "=f"(r.x), "=f"(r.y) : "l"(v)); return r;
}
__device__ __forceinline__ u64 fma2(u64 a, u64 b, u64 c) {
    u64 d; asm("fma.rn.f32x2 %0, %1, %2, %3;" : "=l"(d) : "l"(a), "l"(b), "l"(c)); return d;
}
__device__ __forceinline__ u64 add2(u64 a, u64 b) {
    u64 d; asm("add.rn.f32x2 %0, %1, %2;" : "=l"(d) : "l"(a), "l"(b)); return d;
}
__device__ __forceinline__ u64 lds_b64(unsigned int saddr) {
    u64 d; asm("ld.shared.b64 %0, [%1];" : "=l"(d) : "r"(saddr)); return d;
}
__device__ __forceinline__ void lds_v2b64(unsigned int saddr, u64& a, u64& b) {
    asm("ld.shared.v2.b64 {%0,%1}, [%2];" : "=l"(a), "=l"(b) : "r"(saddr));
}
__device__ __forceinline__ void sts_b64(unsigned int saddr, u64 v) {
    asm volatile("st.shared.b64 [%0], %1;" :: "r"(saddr), "l"(v));
}
__device__ __forceinline__ uint32_t smem_u32(const void* p) {
    uint32_t a;
    asm("{ .reg .u64 t; cvta.to.shared.u64 t, %1; cvt.u32.u64 %0, t; }" : "=r"(a) : "l"(p));
    return a;
}

// ---------------- scratch (static __device__; no allocation) ----------------
__device__ int   g_idx[E_TOT];
__device__ float g_PQS[BB*NN*256];          // [p][0:64)=P, [64:128)=Q, [128:256)=sc pre-BN
__device__ float g_Wcat[256*64];
__device__ float g_W1t[64*128];             // [c][r]
__device__ float g_W2t[128*128];            // [c][r]
__device__ float g_y1[134217728];           // [e_global][128ch] pre-BN layer1
__device__ float g_y2[134217728];           // [e_global][128ch] pre-BN layer2
__device__ float g_part0[SGRID*128];
__device__ float g_partsc[SGRID*256];
__device__ float g_part1[2048*256];
__device__ float g_part2[2048*256];
__device__ float g_a0[64],  g_c0[64];
__device__ float g_a1[128], g_c1[128];
__device__ float g_a2[128], g_c2[128];
__device__ float g_asc[128], g_csc[128];

// ---------------- prep: fold w0 into (Wc, Wn, sc), transpose w1/w2 ----------------
__global__ void prep_kernel(const float* __restrict__ w0, const float* __restrict__ w1,
                            const float* __restrict__ w2, const float* __restrict__ scw) {
    int tid = threadIdx.x;
    for (int i = tid; i < 64*64; i += 256) {
        int r = i >> 6, c = i & 63;
        g_Wcat[r*64 + c] = w0[r*128 + c] - w0[r*128 + 64 + c];
    }
    for (int i = tid; i < 64*64; i += 256) {
        int r = i >> 6, c = i & 63;
        g_Wcat[(64 + r)*64 + c] = w0[r*128 + 64 + c];
    }
    for (int i = tid; i < 128*64; i += 256) {
        int r = i >> 6, c = i & 63;
        g_Wcat[(128 + r)*64 + c] = scw[r*64 + c];
    }
    for (int i = tid; i < 128*64; i += 256) {
        int r = i & 127, c = i >> 7;
        g_W1t[c*128 + r] = w1[r*64 + c];
    }
    for (int i = tid; i < 128*128; i += 256) {
        int r = i & 127, c = i >> 7;
        g_W2t[c*128 + r] = w2[r*128 + c];
    }
}

// ---------------- kNN: 2-D points, 16 nearest excluding self ----------------
__global__ void knn_kernel(const float* __restrict__ pts) {
    __shared__ float px[512], py[512];
    int b = blockIdx.x, n = threadIdx.x;
    px[n] = pts[b*1024 + n];
    py[n] = pts[b*1024 + 512 + n];
    __syncthreads();
    float x0 = px[n], y0v = py[n];
    float bd[KNN]; int bi[KNN];
#pragma unroll
    for (int i = 0; i < KNN; i++) { bd[i] = 1e30f; bi[i] = 0; }
    for (int m = 0; m < 512; m++) {
        if (m == n) continue;
        float dx = px[m] - x0, dy = py[m] - y0v;
        float d = fmaf(dx, dx, dy*dy);
        if (d < bd[KNN-1]) {
            int j = KNN - 1;
            while (j > 0 && bd[j-1] > d) { bd[j] = bd[j-1]; bi[j] = bi[j-1]; j--; }
            bd[j] = d; bi[j] = m;
        }
    }
    int base = (b*512 + n)*KNN;
#pragma unroll
    for (int k = 0; k < KNN; k++) g_idx[base + k] = bi[k];
}

// ---------------- gemm_f: PQS[p][r] = sum_c Wcat[r][c] * f[b][c][n] ----------------
__global__ void gemm_f_kernel(const float* __restrict__ f) {
    __shared__ float Wst[64*65];
    __shared__ float fs[64*65];
    int tid = threadIdx.x;
    int rt0 = blockIdx.x*64, n0 = blockIdx.y*64, b = blockIdx.z;
#pragma unroll
    for (int s = 0; s < 16; s++) {
        int idx = tid + 256*s;
        int c = idx & 63, rl = idx >> 6;
        Wst[c*65 + rl] = g_Wcat[(rt0 + rl)*64 + c];
    }
#pragma unroll
    for (int s = 0; s < 16; s++) {
        int idx = tid + 256*s;
        int nl = idx & 63, c = idx >> 6;
        fs[c*65 + nl] = f[b*32768 + c*512 + n0 + nl];
    }
    __syncthreads();
    int tx = tid & 15, ty = tid >> 4;
    float acc[4][4];
#pragma unroll
    for (int i = 0; i < 4; i++)
#pragma unroll
        for (int j = 0; j < 4; j++) acc[i][j] = 0.f;
#pragma unroll 4
    for (int c = 0; c < 64; c++) {
        float fv[4];
#pragma unroll
        for (int j = 0; j < 4; j++) fv[j] = fs[c*65 + ty*4 + j];
#pragma unroll
        for (int i = 0; i < 4; i++) {
            float w = Wst[c*65 + tx + 16*i];
#pragma unroll
            for (int j = 0; j < 4; j++) acc[i][j] = fmaf(w, fv[j], acc[i][j]);
        }
    }
#pragma unroll
    for (int j = 0; j < 4; j++) {
        float* dst = &g_PQS[(size_t)(b*512 + n0 + ty*4 + j)*256 + rt0 + tx];
#pragma unroll
        for (int i = 0; i < 4; i++) dst[16*i] = acc[i][j];
    }
}

// ---------------- stats of y0 = P[n] + Q[idx] ----------------
__global__ void stats0_kernel() {
    __shared__ float red[128];
    int tid = threadIdx.x;
    int c = tid & 63, q = tid >> 6;
    float s = 0.f, s2 = 0.f;
    for (int p = blockIdx.x*4 + q; p < BB*NN; p += SGRID*4) {
        float Pv = g_PQS[(size_t)p*256 + c];
        size_t rowbase = (size_t)(p & ~511)*256;
#pragma unroll
        for (int k = 0; k < KNN; k++) {
            int m = g_idx[p*KNN + k];
            float y = Pv + g_PQS[rowbase + (size_t)m*256 + 64 + c];
            s += y; s2 += y*y;
        }
    }
    if (tid < 128) red[tid] = 0.f;
    __syncthreads();
    atomicAdd(&red[c], s);
    atomicAdd(&red[64 + c], s2);
    __syncthreads();
    if (tid < 128) g_part0[blockIdx.x*128 + tid] = red[tid];
}

// ---------------- stats of shortcut pre-BN ----------------
__global__ void statssc_kernel() {
    __shared__ float red[256];
    int tid = threadIdx.x;
    int c = tid & 127, q = tid >> 7;
    float s = 0.f, s2 = 0.f;
    for (int p = blockIdx.x*2 + q; p < BB*NN; p += SGRID*2) {
        float v = g_PQS[(size_t)p*256 + 128 + c];
        s += v; s2 += v*v;
    }
    red[tid] = 0.f;
    __syncthreads();
    atomicAdd(&red[c], s);
    atomicAdd(&red[128 + c], s2);
    __syncthreads();
    g_partsc[blockIdx.x*256 + tid] = red[tid];
}

// ---------------- finalize ----------------
__global__ void finalize_kernel(const float* __restrict__ part, int nblocks, int nch,
                                const float* __restrict__ g, const float* __restrict__ bt,
                                float minv, float* a_out, float* c_out) {
    int c = threadIdx.x;
    if (c >= nch) return;
    float s = 0.f, s2 = 0.f;
    for (int i = 0; i < nblocks; i++) {
        s  += part[i*2*nch + c];
        s2 += part[i*2*nch + nch + c];
    }
    float mean = s*minv;
    float var = s2*minv - mean*mean;
    float a = g[c] * rsqrtf(var + 1e-5f);
    a_out[c] = a;
    c_out[c] = bt[c] - a*mean;
}

// ---------------- layer1: FFMA2 GEMM, K=64, dup'd-x smem ----------------
// smem: Wsm[64c][128r] fp32 (32KB) + xsd[64e][64c] u64 dup (32KB)
__global__ void __launch_bounds__(512, 2) layer1_kernel() {
    extern __shared__ char sm[];
    float* Wsm = (float*)sm;
    u64*   xsd = (u64*)(sm + 32768);
    __shared__ float sstat[256];
    int tid = threadIdx.x;
    {
        float4* d = (float4*)Wsm; const float4* s = (const float4*)g_W1t;
        for (int i = tid; i < 2048; i += 512) d[i] = s[i];
    }
    if (tid < 256) sstat[tid] = 0.f;
    __syncthreads();

    int c = tid & 63, eg = tid >> 6;          // fill mapping
    float a0v = g_a0[c], c0v = g_c0[c];
    int rq = tid & 31, eq = tid >> 5;         // gemm mapping: rows 4rq.., e 4eq..
    uint32_t wb = smem_u32(Wsm) + 16u*(uint32_t)rq;
    uint32_t xb0 = smem_u32(xsd) + 2048u*(uint32_t)eq;   // (4eq)*64*8
    uint32_t xfill = smem_u32(xsd) + 8u*(uint32_t)c;
    u64 rs0 = 0, rs1 = 0, rq0 = 0, rq1 = 0;

    for (int t = blockIdx.x; t < NTILES; t += L1GRID) {
        int e0 = t*64;
#pragma unroll
        for (int s = 0; s < 8; s++) {
            int el = eg*8 + s;
            int e = e0 + el;
            int p = e >> 4;
            int m = g_idx[e];
            float Pv = g_PQS[(size_t)p*256 + c];
            float Qv = g_PQS[(size_t)((p & ~511) + m)*256 + 64 + c];
            float v = fmaxf(fmaf(a0v, Pv + Qv, c0v), 0.f);
            sts_b64(xfill + (uint32_t)el*512u, pack2(v, v));
        }
        __syncthreads();
        u64 acc[2][4];
#pragma unroll
        for (int i = 0; i < 2; i++)
#pragma unroll
            for (int j = 0; j < 4; j++) acc[i][j] = 0ull;
        uint32_t wa = wb, xa = xb0;
#pragma unroll 8
        for (int cc = 0; cc < 64; cc++) {
            u64 a0, a1;
            lds_v2b64(wa, a0, a1);
            u64 b0 = lds_b64(xa);
            u64 b1 = lds_b64(xa + 512u);
            u64 b2 = lds_b64(xa + 1024u);
            u64 b3 = lds_b64(xa + 1536u);
            acc[0][0] = fma2(a0, b0, acc[0][0]); acc[1][0] = fma2(a1, b0, acc[1][0]);
            acc[0][1] = fma2(a0, b1, acc[0][1]); acc[1][1] = fma2(a1, b1, acc[1][1]);
            acc[0][2] = fma2(a0, b2, acc[0][2]); acc[1][2] = fma2(a1, b2, acc[1][2]);
            acc[0][3] = fma2(a0, b3, acc[0][3]); acc[1][3] = fma2(a1, b3, acc[1][3]);
            wa += 512u; xa += 8u;
        }
        __syncthreads();
#pragma unroll
        for (int j = 0; j < 4; j++) {
            float2 lo = unpack2(acc[0][j]), hi = unpack2(acc[1][j]);
            float4 v4; v4.x = lo.x; v4.y = lo.y; v4.z = hi.x; v4.w = hi.y;
            *(float4*)&g_y1[(size_t)(e0 + 4*eq + j)*128 + 4*rq] = v4;
            rs0 = add2(rs0, acc[0][j]); rs1 = add2(rs1, acc[1][j]);
            rq0 = fma2(acc[0][j], acc[0][j], rq0); rq1 = fma2(acc[1][j], acc[1][j], rq1);
        }
    }
    {
        float2 s0 = unpack2(rs0), s1 = unpack2(rs1);
        float2 q0 = unpack2(rq0), q1 = unpack2(rq1);
        int ch = 4*rq;
        atomicAdd(&sstat[ch],     s0.x); atomicAdd(&sstat[ch + 1], s0.y);
        atomicAdd(&sstat[ch + 2], s1.x); atomicAdd(&sstat[ch + 3], s1.y);
        atomicAdd(&sstat[128 + ch],     q0.x); atomicAdd(&sstat[128 + ch + 1], q0.y);
        atomicAdd(&sstat[128 + ch + 2], q1.x); atomicAdd(&sstat[128 + ch + 3], q1.y);
    }
    __syncthreads();
    if (tid < 256) g_part1[blockIdx.x*256 + tid] = sstat[tid];
}

// ---------------- layer2: FFMA2 GEMM, K=128, dup'd-x smem ----------------
// smem: Wsm[128c][128r] fp32 (64KB) + xsd[64e][128c] u64 dup (64KB)
__global__ void __launch_bounds__(512, 1) layer2_kernel() {
    extern __shared__ char sm[];
    float* Wsm = (float*)sm;
    u64*   xsd = (u64*)(sm + 65536);
    __shared__ float sstat[256];
    int tid = threadIdx.x;
    {
        float4* d = (float4*)Wsm; const float4* s = (const float4*)g_W2t;
        for (int i = tid; i < 4096; i += 512) d[i] = s[i];
    }
    if (tid < 256) sstat[tid] = 0.f;
    __syncthreads();

    int ch = tid & 127, ebase = tid >> 7;     // fill mapping
    float a1v = g_a1[ch], c1v = g_c1[ch];
    int rq = tid & 31, eq = tid >> 5;         // gemm mapping
    uint32_t wb = smem_u32(Wsm) + 16u*(uint32_t)rq;
    uint32_t xb0 = smem_u32(xsd) + 4096u*(uint32_t)eq;   // (4eq)*128*8
    uint32_t xfill = smem_u32(xsd) + 8u*(uint32_t)ch;
    u64 rs0 = 0, rs1 = 0, rq0 = 0, rq1 = 0;

    for (int t = blockIdx.x; t < NTILES; t += L2GRID) {
        int e0 = t*64;
#pragma unroll
        for (int s = 0; s < 16; s++) {
            int el = ebase + 4*s;
            float v = fmaxf(fmaf(a1v, g_y1[(size_t)(e0 + el)*128 + ch], c1v), 0.f);
            sts_b64(xfill + (uint32_t)el*1024u, pack2(v, v));
        }
        __syncthreads();
        u64 acc[2][4];
#pragma unroll
        for (int i = 0; i < 2; i++)
#pragma unroll
            for (int j = 0; j < 4; j++) acc[i][j] = 0ull;
        uint32_t wa = wb, xa = xb0;
#pragma unroll 8
        for (int cc = 0; cc < 128; cc++) {
            u64 a0, a1;
            lds_v2b64(wa, a0, a1);
            u64 b0 = lds_b64(xa);
            u64 b1 = lds_b64(xa + 1024u);
            u64 b2 = lds_b64(xa + 2048u);
            u64 b3 = lds_b64(xa + 3072u);
            acc[0][0] = fma2(a0, b0, acc[0][0]); acc[1][0] = fma2(a1, b0, acc[1][0]);
            acc[0][1] = fma2(a0, b1, acc[0][1]); acc[1][1] = fma2(a1, b1, acc[1][1]);
            acc[0][2] = fma2(a0, b2, acc[0][2]); acc[1][2] = fma2(a1, b2, acc[1][2]);
            acc[0][3] = fma2(a0, b3, acc[0][3]); acc[1][3] = fma2(a1, b3, acc[1][3]);
            wa += 512u; xa += 8u;
        }
        __syncthreads();
#pragma unroll
        for (int j = 0; j < 4; j++) {
            float2 lo = unpack2(acc[0][j]), hi = unpack2(acc[1][j]);
            float4 v4; v4.x = lo.x; v4.y = lo.y; v4.z = hi.x; v4.w = hi.y;
            *(float4*)&g_y2[(size_t)(e0 + 4*eq + j)*128 + 4*rq] = v4;
            rs0 = add2(rs0, acc[0][j]); rs1 = add2(rs1, acc[1][j]);
            rq0 = fma2(acc[0][j], acc[0][j], rq0); rq1 = fma2(acc[1][j], acc[1][j], rq1);
        }
    }
    {
        float2 s0 = unpack2(rs0), s1 = unpack2(rs1);
        float2 q0 = unpack2(rq0), q1 = unpack2(rq1);
        int c4 = 4*rq;
        atomicAdd(&sstat[c4],     s0.x); atomicAdd(&sstat[c4 + 1], s0.y);
        atomicAdd(&sstat[c4 + 2], s1.x); atomicAdd(&sstat[c4 + 3], s1.y);
        atomicAdd(&sstat[128 + c4],     q0.x); atomicAdd(&sstat[128 + c4 + 1], q0.y);
        atomicAdd(&sstat[128 + c4 + 2], q1.x); atomicAdd(&sstat[128 + c4 + 3], q1.y);
    }
    __syncthreads();
    if (tid < 256) g_part2[blockIdx.x*256 + tid] = sstat[tid];
}

// ---------------- out: fts = mean_k relu(a2*y2+c2); out = relu(asc*sc+csc + fts) ----------------
__global__ void out_kernel(float* __restrict__ out) {
    __shared__ float res[128*33];
    int tid = threadIdx.x;
    int b = blockIdx.x >> 4;
    int n0 = (blockIdx.x & 15)*32;
    int o = tid & 127, ng = tid >> 7;
    float a2v = g_a2[o], c2v = g_c2[o];
    float ascv = g_asc[o], cscv = g_csc[o];
#pragma unroll
    for (int s = 0; s < 16; s++) {
        int nloc = ng + 2*s;
        int p = b*512 + n0 + nloc;
        const float* yr = &g_y2[(size_t)p*KNN*128 + o];
        float fts = 0.f;
#pragma unroll
        for (int k = 0; k < KNN; k++)
            fts += fmaxf(fmaf(a2v, yr[(size_t)k*128], c2v), 0.f);
        fts *= (1.0f/KNN);
        float sc = fmaf(ascv, g_PQS[(size_t)p*256 + 128 + o], cscv);
        res[o*33 + nloc] = fmaxf(sc + fts, 0.f);
    }
    __syncthreads();
#pragma unroll
    for (int s = 0; s < 16; s++) {
        int idx = tid + 256*s;
        int oo = idx >> 5, nl = idx & 31;
        out[(size_t)(b*128 + oo)*512 + n0 + nl] = res[oo*33 + nl];
    }
}

// ---------------- launch ----------------
extern "C" void kernel_launch(void* const* d_in, const int* in_sizes, int n_in,
                              void* d_out, int out_size) {
    const float* pts  = (const float*)d_in[0];
    const float* feat = (const float*)d_in[1];
    const float* w0   = (const float*)d_in[2];
    const float* g0   = (const float*)d_in[3];
    const float* b0   = (const float*)d_in[4];
    const float* w1   = (const float*)d_in[5];
    const float* g1   = (const float*)d_in[6];
    const float* b1   = (const float*)d_in[7];
    const float* w2   = (const float*)d_in[8];
    const float* g2   = (const float*)d_in[9];
    const float* b2   = (const float*)d_in[10];
    const float* scw  = (const float*)d_in[11];
    const float* scg  = (const float*)d_in[12];
    const float* scb  = (const float*)d_in[13];
    float* out = (float*)d_out;

    const int SMEM1 = 65536;    // 32K W + 32K xsd
    const int SMEM2 = 131072;   // 64K W + 64K xsd
    cudaFuncSetAttribute(layer1_kernel, cudaFuncAttributeMaxDynamicSharedMemorySize, SMEM1);
    cudaFuncSetAttribute(layer2_kernel, cudaFuncAttributeMaxDynamicSharedMemorySize, SMEM2);

    float *pa0, *pc0, *pa1, *pc1, *pa2, *pc2, *pasc, *pcsc;
    float *pp0, *ppsc, *pp1, *pp2;
    cudaGetSymbolAddress((void**)&pa0,  g_a0);
    cudaGetSymbolAddress((void**)&pc0,  g_c0);
    cudaGetSymbolAddress((void**)&pa1,  g_a1);
    cudaGetSymbolAddress((void**)&pc1,  g_c1);
    cudaGetSymbolAddress((void**)&pa2,  g_a2);
    cudaGetSymbolAddress((void**)&pc2,  g_c2);
    cudaGetSymbolAddress((void**)&pasc, g_asc);
    cudaGetSymbolAddress((void**)&pcsc, g_csc);
    cudaGetSymbolAddress((void**)&pp0,  g_part0);
    cudaGetSymbolAddress((void**)&ppsc, g_partsc);
    cudaGetSymbolAddress((void**)&pp1,  g_part1);
    cudaGetSymbolAddress((void**)&pp2,  g_part2);

    prep_kernel<<<1, 256>>>(w0, w1, w2, scw);
    knn_kernel<<<BB, 512>>>(pts);
    gemm_f_kernel<<<dim3(4, 8, BB), 256>>>(feat);
    stats0_kernel<<<SGRID, 256>>>();
    statssc_kernel<<<SGRID, 256>>>();
    finalize_kernel<<<1, 64>>>(pp0, SGRID, 64, g0, b0, 1.0f/(float)E_TOT, pa0, pc0);
    finalize_kernel<<<1, 128>>>(ppsc, SGRID, 128, scg, scb, 1.0f/(float)(BB*NN), pasc, pcsc);
    layer1_kernel<<<L1GRID, 512, SMEM1>>>();
    finalize_kernel<<<1, 128>>>(pp1, L1GRID, 128, g1, b1, 1.0f/(float)E_TOT, pa1, pc1);
    layer2_kernel<<<L2GRID, 512, SMEM2>>>();
    finalize_kernel<<<1, 128>>>(pp2, L2GRID, 128, g2, b2, 1.0f/(float)E_TOT, pa2, pc2);
    out_kernel<<<BB*16, 256>>>(out);

    (void)in_sizes; (void)n_in; (void)out_size;
}